// round 6
// baseline (speedup 1.0000x reference)
#include <cuda_runtime.h>
#include <cuda_bf16.h>
#include <math.h>
#include <stdint.h>

// Problem dims
#define BB 4096
#define UU 256
#define DD 128

// GEMM: C[4096, 512] = A[4096, 384]bf16 . B[512, 384]bf16^T, fp32 accum
// K = 3*128 (hi*hi, hi*lo, lo*hi), N = 512 (256 W | 256 bias)
#define NCHUNK 6                 // K chunks of 64 bf16
#define A_CH_U4 1024             // 128 rows x 64 bf16 = 16KB per chunk (uint4)
#define A_MT_U4 (NCHUNK * A_CH_U4)
#define B_NT_U4 (NCHUNK * A_CH_U4)   // B tiles also 128 rows x 64
// smem: per buffer A slice 8KB + B 16KB
#define BUFS 24576
#define GEMM_SMEM (2 * BUFS)     // 49152

__device__ float4 g_cons[UU];            // {nb2, bw, sqrt(ww), 0}
__device__ float  g_nv2[BB];
__device__ uint4  g_A[32 * A_MT_U4];     // 3 MB pre-swizzled A (32 128-row images)
__device__ uint4  g_B[4 * B_NT_U4];      // 384 KB pre-swizzled B (4 ntiles)
__device__ float  g_acc[BB * 512];       // 8 MB raw xw|xb

// ---------------------------------------------------------------------------
// PTX helpers (sm_80-compatible only: cp.async, ldmatrix, mma.sync)
// ---------------------------------------------------------------------------
__device__ __forceinline__ uint32_t smem_u32(const void* p) {
    uint32_t a;
    asm("{ .reg .u64 t; cvta.to.shared.u64 t, %1; cvt.u32.u64 %0, t; }"
        : "=r"(a) : "l"(p));
    return a;
}
#define CP16(dst, src) \
    asm volatile("cp.async.cg.shared.global [%0], [%1], 16;" \
                 :: "r"(dst), "l"(src) : "memory")
#define CP_COMMIT() asm volatile("cp.async.commit_group;" ::: "memory")
#define CP_WAIT1()  asm volatile("cp.async.wait_group 1;" ::: "memory")
#define CP_WAIT0()  asm volatile("cp.async.wait_group 0;" ::: "memory")
#define LDSM4(r0, r1, r2, r3, addr) \
    asm volatile("ldmatrix.sync.aligned.m8n8.x4.shared.b16 {%0,%1,%2,%3}, [%4];" \
                 : "=r"(r0), "=r"(r1), "=r"(r2), "=r"(r3) : "r"(addr))
#define MMA16816(d0, d1, d2, d3, a0, a1, a2, a3, b0, b1) \
    asm volatile("mma.sync.aligned.m16n8k16.row.col.f32.bf16.bf16.f32 " \
                 "{%0,%1,%2,%3}, {%4,%5,%6,%7}, {%8,%9}, {%0,%1,%2,%3};" \
                 : "+f"(d0), "+f"(d1), "+f"(d2), "+f"(d3) \
                 : "r"(a0), "r"(a1), "r"(a2), "r"(a3), "r"(b0), "r"(b1))

__device__ __forceinline__ float fast_sqrt(float v) {
    float r;
    asm("sqrt.approx.f32 %0, %1;" : "=f"(r) : "f"(v));
    return r;
}

__device__ __forceinline__ void split_bf16(float v, __nv_bfloat16& hi, __nv_bfloat16& lo) {
    hi = __float2bfloat16(v);
    lo = __float2bfloat16(v - __bfloat162float(hi));
}

// ---------------------------------------------------------------------------
// prepWB: per-u constants + pre-swizzled B. grid 256 (u), block 128.
// ---------------------------------------------------------------------------
__global__ void prepWB_kernel(const float* __restrict__ W,
                              const float* __restrict__ bias) {
    int u = blockIdx.x;
    int k = threadIdx.x;
    __shared__ float sw[DD], sb[DD];
    __shared__ float red[3][4];

    float b = bias[u * DD + k];
    float w = W[u * DD + k];
    sw[k] = w;
    sb[k] = b;

    float nb2 = b * b, bw = b * w, ww = w * w;
    #pragma unroll
    for (int s = 16; s > 0; s >>= 1) {
        nb2 += __shfl_xor_sync(0xffffffffu, nb2, s);
        bw  += __shfl_xor_sync(0xffffffffu, bw,  s);
        ww  += __shfl_xor_sync(0xffffffffu, ww,  s);
    }
    int wid = k >> 5, lane = k & 31;
    if (lane == 0) { red[0][wid] = nb2; red[1][wid] = bw; red[2][wid] = ww; }
    __syncthreads();
    if (k == 0) {
        float n2  = red[0][0] + red[0][1] + red[0][2] + red[0][3];
        float bw_ = red[1][0] + red[1][1] + red[1][2] + red[1][3];
        float ww_ = red[2][0] + red[2][1] + red[2][2] + red[2][3];
        g_cons[u] = make_float4(n2, bw_, sqrtf(ww_), 0.0f);
    }

    if (k < 32) {
        int which = k >> 4;      // 0 = W, 1 = bias
        int kg    = k & 15;      // 16-element k group (8 bf16 per store)
        const float* s = which ? sb : sw;
        union { __nv_bfloat16 h[8]; uint4 v; } hi, lo;
        #pragma unroll
        for (int i = 0; i < 8; i++)
            split_bf16(s[kg * 8 + i], hi.h[i], lo.h[i]);

        int n = which * 256 + u;
        int ntile = n >> 7, nloc = n & 127;
        int half = kg >> 3, k16 = kg & 7;
        int off16 = (nloc >> 3) * 64 + (nloc & 7) * 8 + (k16 ^ (nloc & 7));
        uint4* base = g_B + ntile * B_NT_U4;
        base[(half)     * A_CH_U4 + off16] = hi.v;
        base[(2 + half) * A_CH_U4 + off16] = lo.v;
        base[(4 + half) * A_CH_U4 + off16] = hi.v;
    }
}

// ---------------------------------------------------------------------------
// prepA: x -> pre-swizzled A splits + per-row nv2. grid 256, block 256.
// ---------------------------------------------------------------------------
__global__ void prepA_kernel(const float* __restrict__ x) {
    int tid = threadIdx.x;
    int r  = tid >> 4;
    int kg = tid & 15;
    int row = blockIdx.x * 16 + r;

    const float4* x4 = reinterpret_cast<const float4*>(x) + row * 32 + kg * 2;
    float4 a = x4[0], c = x4[1];
    float v[8] = {a.x, a.y, a.z, a.w, c.x, c.y, c.z, c.w};

    float s = 0.0f;
    union { __nv_bfloat16 h[8]; uint4 q; } hi, lo;
    #pragma unroll
    for (int i = 0; i < 8; i++) {
        s += v[i] * v[i];
        split_bf16(v[i], hi.h[i], lo.h[i]);
    }
    #pragma unroll
    for (int sh = 8; sh > 0; sh >>= 1)
        s += __shfl_xor_sync(0xffffffffu, s, sh);
    if (kg == 0) g_nv2[row] = s;

    int mtile = row >> 7, rloc = row & 127;
    int half = kg >> 3, k16 = kg & 7;
    int off16 = (rloc >> 3) * 64 + (rloc & 7) * 8 + (k16 ^ (rloc & 7));
    uint4* base = g_A + mtile * A_MT_U4;
    base[(half)     * A_CH_U4 + off16] = hi.q;   // hi (pairs B hi)
    base[(2 + half) * A_CH_U4 + off16] = hi.q;   // hi (pairs B lo)
    base[(4 + half) * A_CH_U4 + off16] = lo.q;   // lo (pairs B hi)
}

// ---------------------------------------------------------------------------
// GEMM: grid (4 ntiles, 64 mtiles64), block 256 (8 warps).
// CTA tile 64(M) x 128(N). Warp tile 32x32.
// 64-row A slice = half of a 128-row image: +512 uint4 for odd mtile64.
// ---------------------------------------------------------------------------
__device__ __forceinline__ void issue_chunk(uint32_t sbase, const uint4* gA,
                                            const uint4* gB, int c, int tid) {
    uint32_t dA = sbase + (c & 1) * BUFS;
    uint32_t dB = dA + 8192;
    const uint4* sa = gA + c * A_CH_U4;
    const uint4* sb = gB + c * A_CH_U4;
    #pragma unroll
    for (int i = 0; i < 2; i++) CP16(dA + (tid + 256 * i) * 16, sa + tid + 256 * i);
    #pragma unroll
    for (int i = 0; i < 4; i++) CP16(dB + (tid + 256 * i) * 16, sb + tid + 256 * i);
    CP_COMMIT();
}

__global__ void __launch_bounds__(256)
gemm_kernel() {
    extern __shared__ __align__(1024) char smem[];
    uint32_t sbase = smem_u32(smem);
    const int tid = threadIdx.x;
    const int wid = tid >> 5, lane = tid & 31;
    const int ntile = blockIdx.x, mt64 = blockIdx.y;

    const uint4* gA = g_A + (mt64 >> 1) * A_MT_U4 + (mt64 & 1) * 512;
    const uint4* gB = g_B + ntile * B_NT_U4;

    const int m0 = (wid & 1) * 32;
    const int n0 = (wid >> 1) * 32;
    const int rowa  = m0 + (lane & 15);
    const int abase = (rowa >> 3) * 64 + (rowa & 7) * 8;
    const int aswz  = rowa & 7;
    const int akus  = lane >> 4;
    const int rowb  = n0 + (lane & 7) + ((lane >> 4) << 3);
    const int bbase = (rowb >> 3) * 64 + (rowb & 7) * 8;
    const int bswz  = rowb & 7;
    const int bkus  = (lane >> 3) & 1;

    float d[2][4][4];
    #pragma unroll
    for (int i = 0; i < 2; i++)
        #pragma unroll
        for (int j = 0; j < 4; j++)
            #pragma unroll
            for (int q = 0; q < 4; q++) d[i][j][q] = 0.0f;

    issue_chunk(sbase, gA, gB, 0, tid);

    #pragma unroll
    for (int c = 0; c < NCHUNK; c++) {
        if (c < NCHUNK - 1) {
            issue_chunk(sbase, gA, gB, c + 1, tid);
            CP_WAIT1();
        } else {
            CP_WAIT0();
        }
        __syncthreads();

        uint32_t aB = sbase + (c & 1) * BUFS;
        uint32_t bB = aB + 8192;

        #pragma unroll
        for (int kk = 0; kk < 4; kk++) {
            uint32_t af[2][4];
            #pragma unroll
            for (int mf = 0; mf < 2; mf++) {
                uint32_t addr = aB + ((abase + mf * 128 +
                                       ((2 * kk + akus) ^ aswz)) << 4);
                LDSM4(af[mf][0], af[mf][1], af[mf][2], af[mf][3], addr);
            }
            uint32_t bf[2][4];
            #pragma unroll
            for (int h = 0; h < 2; h++) {
                uint32_t addr = bB + ((bbase + h * 128 +
                                       ((2 * kk + bkus) ^ bswz)) << 4);
                LDSM4(bf[h][0], bf[h][1], bf[h][2], bf[h][3], addr);
            }
            #pragma unroll
            for (int mf = 0; mf < 2; mf++)
                #pragma unroll
                for (int nf = 0; nf < 4; nf++)
                    MMA16816(d[mf][nf][0], d[mf][nf][1], d[mf][nf][2], d[mf][nf][3],
                             af[mf][0], af[mf][1], af[mf][2], af[mf][3],
                             bf[nf >> 1][(nf & 1) * 2], bf[nf >> 1][(nf & 1) * 2 + 1]);
        }
        __syncthreads();
    }

    const int rbase = mt64 * 64 + m0 + (lane >> 2);
    const int cbase = ntile * 128 + n0 + 2 * (lane & 3);
    #pragma unroll
    for (int mf = 0; mf < 2; mf++)
        #pragma unroll
        for (int nf = 0; nf < 4; nf++) {
            int row = rbase + mf * 16;
            int col = cbase + nf * 8;
            *reinterpret_cast<float2*>(&g_acc[row * 512 + col]) =
                make_float2(d[mf][nf][0], d[mf][nf][1]);
            *reinterpret_cast<float2*>(&g_acc[(row + 8) * 512 + col]) =
                make_float2(d[mf][nf][2], d[mf][nf][3]);
        }
}

// ---------------------------------------------------------------------------
// Epilogue: hyperbolic math + softmax in base-2 space.
// grid 1024 (4 rows each), block 256 (u = tid). Warps 0-3 do row softmax.
// ---------------------------------------------------------------------------
#define UPAD 257
#define EROWS 4
__global__ void __launch_bounds__(256)
epilogue_kernel(float* __restrict__ out) {
    __shared__ float slog[EROWS * UPAD];
    __shared__ float snv2[EROWS];
    const int u  = threadIdx.x;
    const int b0 = blockIdx.x * EROWS;

    if (u < EROWS) snv2[u] = g_nv2[b0 + u];

    float4 cs  = g_cons[u];
    float  nb2 = cs.x, bw = cs.y, sww = cs.z;
    float  beta = 1.0f - nb2;
    float  bsw  = beta * sww;
    float  twosww = 2.0f * sww;
    __syncthreads();

    float lg[EROWS];
    #pragma unroll
    for (int r = 0; r < EROWS; r++) {
        float xw  = g_acc[(b0 + r) * 512 + u];
        float xb  = g_acc[(b0 + r) * 512 + 256 + u];
        float nv2 = snv2[r];
        float xy = -xb;
        float t2 = 2.0f * xy;
        float alpha = 1.0f + t2 + nv2;
        float dd = 1.0f + t2 + nb2 * nv2;
        float num = 2.0f * beta * (beta * xw - alpha * bw);
        float smm_num = alpha * alpha * nb2 + 2.0f * alpha * beta * xy
                        + beta * beta * nv2;
        float arg = __fdividef(num * dd, (dd * dd - smm_num) * bsw);
        float s = arg + fast_sqrt(fmaf(arg, arg, 1.0f));
        lg[r] = twosww * __log2f(s);
    }
    #pragma unroll
    for (int r = 0; r < EROWS; r++)
        slog[r * UPAD + u] = lg[r];
    __syncthreads();

    // softmax: warps 0-3 each own one row
    int wid = u >> 5, lane = u & 31;
    if (wid < EROWS) {
        int r = wid;
        float v[8];
        float m = -1e30f;
        #pragma unroll
        for (int j = 0; j < 8; j++) {
            v[j] = slog[r * UPAD + lane + 32 * j];
            m = fmaxf(m, v[j]);
        }
        #pragma unroll
        for (int sh = 16; sh > 0; sh >>= 1)
            m = fmaxf(m, __shfl_xor_sync(0xffffffffu, m, sh));
        float e[8], s = 0.0f;
        #pragma unroll
        for (int j = 0; j < 8; j++) { e[j] = exp2f(v[j] - m); s += e[j]; }
        #pragma unroll
        for (int sh = 16; sh > 0; sh >>= 1)
            s += __shfl_xor_sync(0xffffffffu, s, sh);
        float inv = __fdividef(1.0f, s);
        #pragma unroll
        for (int j = 0; j < 8; j++)
            out[(b0 + r) * UU + lane + 32 * j] = e[j] * inv;
    }
}

// ---------------------------------------------------------------------------
extern "C" void kernel_launch(void* const* d_in, const int* in_sizes, int n_in,
                              void* d_out, int out_size) {
    const float* x    = (const float*)d_in[0];
    const float* W    = (const float*)d_in[1];
    const float* bias = (const float*)d_in[2];
    float* out = (float*)d_out;

    cudaFuncSetAttribute(gemm_kernel,
                         cudaFuncAttributeMaxDynamicSharedMemorySize, GEMM_SMEM);

    prepWB_kernel<<<UU, DD>>>(W, bias);
    prepA_kernel<<<BB / 16, 256>>>(x);
    gemm_kernel<<<dim3(4, 64), 256, GEMM_SMEM>>>();
    epilogue_kernel<<<BB / EROWS, 256>>>(out);
}

// round 7
// speedup vs baseline: 1.1347x; 1.1347x over previous
#include <cuda_runtime.h>
#include <cuda_bf16.h>
#include <math.h>
#include <stdint.h>

// Problem dims
#define BB 4096
#define UU 256
#define DD 128

// GEMM: C[4096, 512] = A[4096, 384]bf16 . B[512, 384]bf16^T, fp32 accum
// K = 3*128 (hi*hi, hi*lo, lo*hi). B columns PAIR-interleaved: col 2u = W_u,
// col 2u+1 = bias_u, so each MMA (d0,d1) = (xw, xb) for one u.
#define NCHUNK 6                 // K chunks of 64 bf16
#define A_CH_U4 1024             // 128 rows x 64 bf16 = 16KB per chunk (uint4)
#define A_MT_U4 (NCHUNK * A_CH_U4)
#define B_NT_U4 (NCHUNK * A_CH_U4)
#define GEMM_SMEM 196608         // all-K: A 96KB + B 96KB

__device__ float4 g_cons[UU];            // {nb2, bw, sqrt(ww), 0}
__device__ float  g_nv2[BB];
__device__ uint4  g_A[32 * A_MT_U4];     // 3 MB pre-swizzled A (32 mtiles)
__device__ uint4  g_B[4 * B_NT_U4];      // 384 KB pre-swizzled B (4 ntiles)
__device__ float  g_acc[BB * 512];       // 8 MB paired (xw, xb)

// ---------------------------------------------------------------------------
// PTX helpers (sm_80-compatible only: cp.async, ldmatrix, mma.sync)
// ---------------------------------------------------------------------------
__device__ __forceinline__ uint32_t smem_u32(const void* p) {
    uint32_t a;
    asm("{ .reg .u64 t; cvta.to.shared.u64 t, %1; cvt.u32.u64 %0, t; }"
        : "=r"(a) : "l"(p));
    return a;
}
#define CP16(dst, src) \
    asm volatile("cp.async.cg.shared.global [%0], [%1], 16;" \
                 :: "r"(dst), "l"(src) : "memory")
#define CP_COMMIT() asm volatile("cp.async.commit_group;" ::: "memory")
#define CP_WAITG(n) asm volatile("cp.async.wait_group " #n ";" ::: "memory")
#define LDSM4(r0, r1, r2, r3, addr) \
    asm volatile("ldmatrix.sync.aligned.m8n8.x4.shared.b16 {%0,%1,%2,%3}, [%4];" \
                 : "=r"(r0), "=r"(r1), "=r"(r2), "=r"(r3) : "r"(addr))
#define MMA16816(d0, d1, d2, d3, a0, a1, a2, a3, b0, b1) \
    asm volatile("mma.sync.aligned.m16n8k16.row.col.f32.bf16.bf16.f32 " \
                 "{%0,%1,%2,%3}, {%4,%5,%6,%7}, {%8,%9}, {%0,%1,%2,%3};" \
                 : "+f"(d0), "+f"(d1), "+f"(d2), "+f"(d3) \
                 : "r"(a0), "r"(a1), "r"(a2), "r"(a3), "r"(b0), "r"(b1))

__device__ __forceinline__ float fast_sqrt(float v) {
    float r;
    asm("sqrt.approx.f32 %0, %1;" : "=f"(r) : "f"(v));
    return r;
}

__device__ __forceinline__ void split_bf16(float v, __nv_bfloat16& hi, __nv_bfloat16& lo) {
    hi = __float2bfloat16(v);
    lo = __float2bfloat16(v - __bfloat162float(hi));
}

// ---------------------------------------------------------------------------
// Merged prep: blocks 0-255 do A (x split + nv2), blocks 256-511 do W/bias.
// Block 256 threads.
// ---------------------------------------------------------------------------
__global__ void prep_kernel(const float* __restrict__ x,
                            const float* __restrict__ W,
                            const float* __restrict__ bias) {
    const int tid = threadIdx.x;
    if (blockIdx.x < 256) {
        // ---- prepA: 16 rows per block ----
        int r  = tid >> 4;
        int kg = tid & 15;
        int row = blockIdx.x * 16 + r;

        const float4* x4 = reinterpret_cast<const float4*>(x) + row * 32 + kg * 2;
        float4 a = x4[0], c = x4[1];
        float v[8] = {a.x, a.y, a.z, a.w, c.x, c.y, c.z, c.w};

        float s = 0.0f;
        union { __nv_bfloat16 h[8]; uint4 q; } hi, lo;
        #pragma unroll
        for (int i = 0; i < 8; i++) {
            s += v[i] * v[i];
            split_bf16(v[i], hi.h[i], lo.h[i]);
        }
        #pragma unroll
        for (int sh = 8; sh > 0; sh >>= 1)
            s += __shfl_xor_sync(0xffffffffu, s, sh);
        if (kg == 0) g_nv2[row] = s;

        int mtile = row >> 7, rloc = row & 127;
        int half = kg >> 3, k16 = kg & 7;
        int off16 = (rloc >> 3) * 64 + (rloc & 7) * 8 + (k16 ^ (rloc & 7));
        uint4* base = g_A + mtile * A_MT_U4;
        base[(half)     * A_CH_U4 + off16] = hi.q;   // hi (pairs B hi)
        base[(2 + half) * A_CH_U4 + off16] = hi.q;   // hi (pairs B lo)
        base[(4 + half) * A_CH_U4 + off16] = lo.q;   // lo (pairs B hi)
    } else {
        // ---- prepWB: one u per block ----
        int u = blockIdx.x - 256;
        int k = tid;
        __shared__ float sw[DD], sb[DD];
        __shared__ float red[3][4];

        if (k < DD) {
            float b = bias[u * DD + k];
            float w = W[u * DD + k];
            sw[k] = w;
            sb[k] = b;
            float nb2 = b * b, bw = b * w, ww = w * w;
            #pragma unroll
            for (int s = 16; s > 0; s >>= 1) {
                nb2 += __shfl_xor_sync(0xffffffffu, nb2, s);
                bw  += __shfl_xor_sync(0xffffffffu, bw,  s);
                ww  += __shfl_xor_sync(0xffffffffu, ww,  s);
            }
            int wid = k >> 5, lane = k & 31;
            if (lane == 0) { red[0][wid] = nb2; red[1][wid] = bw; red[2][wid] = ww; }
        }
        __syncthreads();
        if (k == 0) {
            float n2  = red[0][0] + red[0][1] + red[0][2] + red[0][3];
            float bw_ = red[1][0] + red[1][1] + red[1][2] + red[1][3];
            float ww_ = red[2][0] + red[2][1] + red[2][2] + red[2][3];
            g_cons[u] = make_float4(n2, bw_, sqrtf(ww_), 0.0f);
        }
        if (k < 32) {
            int which = k >> 4;      // 0 = W (even col), 1 = bias (odd col)
            int kg    = k & 15;
            const float* s = which ? sb : sw;
            union { __nv_bfloat16 h[8]; uint4 v; } hi, lo;
            #pragma unroll
            for (int i = 0; i < 8; i++)
                split_bf16(s[kg * 8 + i], hi.h[i], lo.h[i]);

            int n = 2 * u + which;               // PAIRED layout
            int ntile = n >> 7, nloc = n & 127;
            int half = kg >> 3, k16 = kg & 7;
            int off16 = (nloc >> 3) * 64 + (nloc & 7) * 8 + (k16 ^ (nloc & 7));
            uint4* base = g_B + ntile * B_NT_U4;
            base[(half)     * A_CH_U4 + off16] = hi.v;
            base[(2 + half) * A_CH_U4 + off16] = lo.v;
            base[(4 + half) * A_CH_U4 + off16] = hi.v;
        }
    }
}

// ---------------------------------------------------------------------------
// GEMM: grid (4 ntiles, 32 mtiles), block 256 (8 warps). CTA tile 128x128.
// All-K smem residence: 6 cp.async groups issued upfront, progressive waits.
// ---------------------------------------------------------------------------
__global__ void __launch_bounds__(256)
gemm_kernel() {
    extern __shared__ __align__(1024) char smem[];
    uint32_t sbase = smem_u32(smem);
    const int tid = threadIdx.x;
    const int wid = tid >> 5, lane = tid & 31;
    const int ntile = blockIdx.x, mtile = blockIdx.y;

    const uint4* gA = g_A + mtile * A_MT_U4;
    const uint4* gB = g_B + ntile * B_NT_U4;

    // issue all chunks: group c = A chunk c + B chunk c
    #pragma unroll
    for (int c = 0; c < NCHUNK; c++) {
        uint32_t dA = sbase + c * 16384;
        uint32_t dB = sbase + 98304 + c * 16384;
        const uint4* sa = gA + c * A_CH_U4;
        const uint4* sb = gB + c * A_CH_U4;
        #pragma unroll
        for (int i = 0; i < 4; i++) CP16(dA + (tid + 256 * i) * 16, sa + tid + 256 * i);
        #pragma unroll
        for (int i = 0; i < 4; i++) CP16(dB + (tid + 256 * i) * 16, sb + tid + 256 * i);
        CP_COMMIT();
    }

    const int m0 = (wid & 1) * 64;
    const int n0 = (wid >> 1) * 32;
    const int rowa  = m0 + (lane & 15);
    const int abase = (rowa >> 3) * 64 + (rowa & 7) * 8;
    const int aswz  = rowa & 7;
    const int akus  = lane >> 4;
    const int rowb  = n0 + (lane & 7) + ((lane >> 4) << 3);
    const int bbase = (rowb >> 3) * 64 + (rowb & 7) * 8;
    const int bswz  = rowb & 7;
    const int bkus  = (lane >> 3) & 1;

    float d[4][4][4];
    #pragma unroll
    for (int i = 0; i < 4; i++)
        #pragma unroll
        for (int j = 0; j < 4; j++)
            #pragma unroll
            for (int q = 0; q < 4; q++) d[i][j][q] = 0.0f;

    #pragma unroll
    for (int c = 0; c < NCHUNK; c++) {
        switch (c) {              // progressive in-order group completion
            case 0: CP_WAITG(5); break;
            case 1: CP_WAITG(4); break;
            case 2: CP_WAITG(3); break;
            case 3: CP_WAITG(2); break;
            case 4: CP_WAITG(1); break;
            default: CP_WAITG(0); break;
        }
        __syncthreads();

        uint32_t aB = sbase + c * 16384;
        uint32_t bB = sbase + 98304 + c * 16384;

        #pragma unroll
        for (int kk = 0; kk < 4; kk++) {
            uint32_t af[4][4];
            #pragma unroll
            for (int mf = 0; mf < 4; mf++) {
                uint32_t addr = aB + ((abase + mf * 128 +
                                       ((2 * kk + akus) ^ aswz)) << 4);
                LDSM4(af[mf][0], af[mf][1], af[mf][2], af[mf][3], addr);
            }
            uint32_t bf[2][4];
            #pragma unroll
            for (int h = 0; h < 2; h++) {
                uint32_t addr = bB + ((bbase + h * 128 +
                                       ((2 * kk + bkus) ^ bswz)) << 4);
                LDSM4(bf[h][0], bf[h][1], bf[h][2], bf[h][3], addr);
            }
            #pragma unroll
            for (int mf = 0; mf < 4; mf++)
                #pragma unroll
                for (int nf = 0; nf < 4; nf++)
                    MMA16816(d[mf][nf][0], d[mf][nf][1], d[mf][nf][2], d[mf][nf][3],
                             af[mf][0], af[mf][1], af[mf][2], af[mf][3],
                             bf[nf >> 1][(nf & 1) * 2], bf[nf >> 1][(nf & 1) * 2 + 1]);
        }
    }

    // store: (d0,d1) = (xw,xb) pair at even col -> stays paired in g_acc
    const int rbase = mtile * 128 + m0 + (lane >> 2);
    const int cbase = ntile * 128 + n0 + 2 * (lane & 3);
    #pragma unroll
    for (int mf = 0; mf < 4; mf++)
        #pragma unroll
        for (int nf = 0; nf < 4; nf++) {
            int row = rbase + mf * 16;
            int col = cbase + nf * 8;
            *reinterpret_cast<float2*>(&g_acc[row * 512 + col]) =
                make_float2(d[mf][nf][0], d[mf][nf][1]);
            *reinterpret_cast<float2*>(&g_acc[(row + 8) * 512 + col]) =
                make_float2(d[mf][nf][2], d[mf][nf][3]);
        }
}

// ---------------------------------------------------------------------------
// Epilogue: hyperbolic math + softmax (base-2). grid 2048 (2 rows), block 256.
// Paired g_acc: one float2 LDG yields (xw, xb).
// ---------------------------------------------------------------------------
#define UPAD 257
#define EROWS 2
__global__ void __launch_bounds__(256)
epilogue_kernel(float* __restrict__ out) {
    __shared__ float slog[EROWS * UPAD];
    __shared__ float snv2[EROWS];
    const int u  = threadIdx.x;
    const int b0 = blockIdx.x * EROWS;

    if (u < EROWS) snv2[u] = g_nv2[b0 + u];

    float4 cs  = g_cons[u];
    float  nb2 = cs.x, bw = cs.y, sww = cs.z;
    float  beta = 1.0f - nb2;
    float  bsw  = beta * sww;
    float  twosww = 2.0f * sww;
    __syncthreads();

    const float2* acc2 = reinterpret_cast<const float2*>(g_acc);
    float lg[EROWS];
    #pragma unroll
    for (int r = 0; r < EROWS; r++) {
        float2 p = acc2[(b0 + r) * 256 + u];
        float xw = p.x, xb = p.y;
        float nv2 = snv2[r];
        float xy = -xb;
        float t2 = 2.0f * xy;
        float alpha = 1.0f + t2 + nv2;
        float dd = 1.0f + t2 + nb2 * nv2;
        float num = 2.0f * beta * (beta * xw - alpha * bw);
        float smm_num = alpha * alpha * nb2 + 2.0f * alpha * beta * xy
                        + beta * beta * nv2;
        float arg = __fdividef(num * dd, (dd * dd - smm_num) * bsw);
        float s = arg + fast_sqrt(fmaf(arg, arg, 1.0f));
        lg[r] = twosww * __log2f(s);
    }
    #pragma unroll
    for (int r = 0; r < EROWS; r++)
        slog[r * UPAD + u] = lg[r];
    __syncthreads();

    // softmax: warps 0..EROWS-1 each own one row
    int wid = u >> 5, lane = u & 31;
    if (wid < EROWS) {
        int r = wid;
        float v[8];
        float m = -1e30f;
        #pragma unroll
        for (int j = 0; j < 8; j++) {
            v[j] = slog[r * UPAD + lane + 32 * j];
            m = fmaxf(m, v[j]);
        }
        #pragma unroll
        for (int sh = 16; sh > 0; sh >>= 1)
            m = fmaxf(m, __shfl_xor_sync(0xffffffffu, m, sh));
        float e[8], s = 0.0f;
        #pragma unroll
        for (int j = 0; j < 8; j++) { e[j] = exp2f(v[j] - m); s += e[j]; }
        #pragma unroll
        for (int sh = 16; sh > 0; sh >>= 1)
            s += __shfl_xor_sync(0xffffffffu, s, sh);
        float inv = __fdividef(1.0f, s);
        #pragma unroll
        for (int j = 0; j < 8; j++)
            out[(b0 + r) * UU + lane + 32 * j] = e[j] * inv;
    }
}

// ---------------------------------------------------------------------------
extern "C" void kernel_launch(void* const* d_in, const int* in_sizes, int n_in,
                              void* d_out, int out_size) {
    const float* x    = (const float*)d_in[0];
    const float* W    = (const float*)d_in[1];
    const float* bias = (const float*)d_in[2];
    float* out = (float*)d_out;

    cudaFuncSetAttribute(gemm_kernel,
                         cudaFuncAttributeMaxDynamicSharedMemorySize, GEMM_SMEM);

    prep_kernel<<<512, 256>>>(x, W, bias);
    gemm_kernel<<<dim3(4, 32), 256, GEMM_SMEM>>>();
    epilogue_kernel<<<BB / EROWS, 256>>>(out);
}